// round 12
// baseline (speedup 1.0000x reference)
#include <cuda_runtime.h>
#include <math.h>
#include <stdint.h>

#define BB 2048
#define LL 1024
#define HH 64
#define TT 16
#define GSTR 72     // Gn hi/lo table row stride (u32): bank = 8*row+gid -> conflict-light gathers
#define ASTR 20     // sA row stride (u32): conflict-free A fragment loads
#define PSTR 68     // sPT row stride (floats): conflict-free transposed dump

// ---------------- precomputed tables ----------------
__device__ float d_K[HH * HH];
__device__ float d_g[HH];
__device__ float d_Gn[HH * HH];      // Gn[v][j] = -a_v * (k_v . k_j)
__device__ uint32_t d_GnHi[HH * HH]; // tf32 high part (bits)
__device__ uint32_t d_GnLo[HH * HH]; // tf32 residual part (bits)
__device__ float d_r[HH];            // r_v = ||k_v||^2 + 1e-6
__device__ float d_Y[HH * HH];
__device__ float d_Z[HH * HH];
__device__ float d_bias2[HH];

// ---------------- precompute A ----------------
__global__ void __launch_bounds__(128) prekA(
    const float* __restrict__ embed_W, const float* __restrict__ ff_w1, const float* __restrict__ ff_b1,
    const float* __restrict__ ff_w2,   const float* __restrict__ ff_b2, const float* __restrict__ ln_g,
    const float* __restrict__ ln_b,    const float* __restrict__ gate_w1, const float* __restrict__ gate_b1,
    const float* __restrict__ gate_w2, const float* __restrict__ gate_b2)
{
    int v = blockIdx.x;
    int tid = threadIdx.x;
    __shared__ float se[HH];
    __shared__ float sz[2 * HH];
    __shared__ float sk[HH];
    __shared__ float sh[16];
    __shared__ float sred[4];

    if (tid < HH) se[tid] = embed_W[v * HH + tid];
    __syncthreads();

    {
        float z = ff_b1[tid];
        #pragma unroll 8
        for (int i = 0; i < HH; i++) z = fmaf(se[i], ff_w1[i * (2 * HH) + tid], z);
        sz[tid] = fmaxf(z, 0.0f);
    }
    __syncthreads();

    if (tid < HH) {
        float ff = ff_b2[tid];
        #pragma unroll 8
        for (int j = 0; j < 2 * HH; j++) ff = fmaf(sz[j], ff_w2[j * HH + tid], ff);
        float x = se[tid] + ff;

        float s = x;
        #pragma unroll
        for (int o = 16; o > 0; o >>= 1) s += __shfl_xor_sync(0xffffffffu, s, o);
        if ((tid & 31) == 0) sred[tid >> 5] = s;
        __syncwarp();
        __syncthreads();
        float mu = (sred[0] + sred[1]) * (1.0f / HH);

        float d = x - mu;
        float sv = d * d;
        #pragma unroll
        for (int o = 16; o > 0; o >>= 1) sv += __shfl_xor_sync(0xffffffffu, sv, o);
        if ((tid & 31) == 0) sred[2 + (tid >> 5)] = sv;
        __syncwarp();
        __syncthreads();
        float var = (sred[2] + sred[3]) * (1.0f / HH);
        float inv = rsqrtf(var + 1e-5f);
        float k = d * inv * ln_g[tid] + ln_b[tid];
        sk[tid] = k;
        d_K[v * HH + tid] = k;
    }
    __syncthreads();

    if (tid < 16) {
        float hj = gate_b1[tid];
        #pragma unroll 8
        for (int i = 0; i < HH; i++) hj = fmaf(sk[i], gate_w1[i * 16 + tid], hj);
        sh[tid] = fmaxf(hj, 0.0f);
    }
    __syncthreads();
    if (tid == 0) {
        float gz = gate_b2[0];
        #pragma unroll
        for (int j = 0; j < 16; j++) gz = fmaf(sh[j], gate_w2[j], gz);
        d_g[v] = 1.0f / (1.0f + expf(-gz));
    }
}

// ---------------- tf32 split helper ----------------
__device__ __forceinline__ uint32_t tf32b(float x) {
    uint32_t r;
    asm("cvt.rna.tf32.f32 %0, %1;" : "=r"(r) : "f"(x));
    return r;
}

// ---------------- precompute B ----------------
__global__ void __launch_bounds__(64) prekB(
    const float* __restrict__ read_w, const float* __restrict__ read_b,
    const float* __restrict__ out_w,  const float* __restrict__ out_b)
{
    int v = blockIdx.x;
    int u = threadIdx.x;
    __shared__ float skv[HH];
    __shared__ float sdiag;

    skv[u] = d_K[v * HH + u];
    __syncthreads();

    float s = 0.0f;
    #pragma unroll 8
    for (int i = 0; i < HH; i++) s = fmaf(skv[i], d_K[u * HH + i], s);
    if (u == v) sdiag = s;
    __syncthreads();

    float denom = sdiag + 1e-6f;
    float a = d_g[v] / denom;
    float gn = -a * s;
    d_Gn[v * HH + u] = gn;
    uint32_t hb = tf32b(gn);
    d_GnHi[v * HH + u] = hb;
    d_GnLo[v * HH + u] = tf32b(gn - __uint_as_float(hb));
    if (u == v) d_r[v] = denom;

    float y = 0.0f;
    #pragma unroll 8
    for (int m = 0; m < HH; m++) y = fmaf(read_w[v * HH + m], out_w[m * HH + u], y);
    d_Y[v * HH + u] = y;

    if (v == 0) {
        float b = out_b[u];
        #pragma unroll 8
        for (int m = 0; m < HH; m++) b = fmaf(read_b[m], out_w[m * HH + u], b);
        d_bias2[u] = b;
    }
}

// ---------------- precompute C ----------------
__global__ void __launch_bounds__(64) prekC()
{
    int v = blockIdx.x;
    int n = threadIdx.x;
    __shared__ float skv[HH];
    skv[n] = d_K[v * HH + n];
    __syncthreads();
    float s = 0.0f;
    #pragma unroll 8
    for (int h = 0; h < HH; h++) s = fmaf(skv[h], d_Y[h * HH + n], s);
    d_Z[v * HH + n] = s;
}

// ---------------- mma helper (baseline PTX, sm_80+) ----------------
__device__ __forceinline__ void mma8(float* c,
                                     uint32_t a0, uint32_t a1, uint32_t a2, uint32_t a3,
                                     uint32_t b0, uint32_t b1) {
    asm("mma.sync.aligned.m16n8k8.row.col.f32.tf32.tf32.f32 "
        "{%0,%1,%2,%3},{%4,%5,%6,%7},{%8,%9},{%0,%1,%2,%3};"
        : "+f"(c[0]), "+f"(c[1]), "+f"(c[2]), "+f"(c[3])
        : "r"(a0), "r"(a1), "r"(a2), "r"(a3), "r"(b0), "r"(b1));
}

// ---------------- dynamic shared layout ----------------
struct SMemS {
    uint32_t GnHi[HH * GSTR];   // persistent tf32-hi bits, padded rows
    uint32_t GnLo[HH * GSTR];   // persistent tf32-lo bits
    float    sPT[HH * PSTR];    // P transposed: row = col-of-P
    uint32_t sAhi[HH * ASTR];   // S^T hi bits, row h, col u
    uint32_t sAlo[HH * ASTR];   // S^T lo bits
    float    sC[TT * TT];       // triangular coeffs
    float    sr[HH];
    int      stok[2][TT];
    short    tri[120];          // (t | u<<8) for strictly-lower-triangular entries
};
#define SMEM_BYTES ((int)sizeof(SMemS))

// ---------------- scan: chunked delta rule, P in mma register fragments ----------------
__global__ void __launch_bounds__(128) scan_mma(const int* __restrict__ seq, float* __restrict__ out)
{
    extern __shared__ __align__(16) char dynsmem[];
    SMemS* sm = (SMemS*)dynsmem;

    int tid = threadIdx.x;
    int warp = tid >> 5, lane = tid & 31;
    int gid = lane >> 2, tig = lane & 3;
    int m0 = warp * 16;
    long b = blockIdx.x;
    const int* seqb = seq + b * LL;

    // persistent tables: copy pre-split Gn (no cvt in this kernel)
    #pragma unroll 1
    for (int i = tid; i < HH * HH; i += 128) {
        int r = i >> 6, cc = i & 63;
        sm->GnHi[r * GSTR + cc] = d_GnHi[i];
        sm->GnLo[r * GSTR + cc] = d_GnLo[i];
    }
    if (tid < HH) sm->sr[tid] = d_r[tid];
    if (tid == 0) {
        int e = 0;
        for (int t = 1; t < TT; t++)
            for (int u = 0; u < t; u++) sm->tri[e++] = (short)(t | (u << 8));
    }

    float Cacc[8][4];
    #pragma unroll
    for (int nt = 0; nt < 8; nt++)
        #pragma unroll
        for (int q = 0; q < 4; q++) Cacc[nt][q] = 0.0f;

    const int nsteps = LL - 1;               // 1023
    const int NCH = (nsteps + TT - 1) / TT;  // 64

    int ntok = (tid < TT) ? ((tid < nsteps) ? seqb[tid] : 0) : 0;
    __syncthreads();

    #pragma unroll 1
    for (int c = 0; c < NCH; c++) {
        int c0 = c * TT;
        int cb = c & 1;

        // P1: publish this chunk's tokens; prefetch next chunk's
        if (tid < TT) {
            sm->stok[cb][tid] = ntok;
            int p = c0 + TT + tid;
            ntok = (p < nsteps) ? seqb[p] : 0;
        }
        __syncthreads();   // BAR 1: tokens visible; prev chunk fully retired

        // P3a: dump P (pre-update) transposed to sPT. Conflict-free STS.32.
        #pragma unroll
        for (int nt = 0; nt < 8; nt++) {
            int r0 = m0 + gid, r1 = r0 + 8;
            int cA = nt * 8 + tig * 2, cB = cA + 1;
            sm->sPT[cA * PSTR + r0] = Cacc[nt][0];
            sm->sPT[cB * PSTR + r0] = Cacc[nt][1];
            sm->sPT[cA * PSTR + r1] = Cacc[nt][2];
            sm->sPT[cB * PSTR + r1] = Cacc[nt][3];
        }
        // P3b: warps 2-3 build C[t][u] = Gn[v_u][v_t] (u < t), 120 entries via smem LUT
        if (warp >= 2) {
            int j = tid - 64;
            #pragma unroll 1
            for (int e = j; e < 120; e += 64) {
                int pk = sm->tri[e];
                int t = pk & 0xff, u = pk >> 8;
                int idx = sm->stok[cb][u] * GSTR + sm->stok[cb][t];
                sm->sC[t * TT + u] = __uint_as_float(sm->GnHi[idx]) + __uint_as_float(sm->GnLo[idx]);
            }
        }
        __syncthreads();   // BAR 2: sPT + sC ready

        // P4: warps 0-1 solve; thread h handles component h.
        if (warp < 2) {
            int h = tid;
            float s[TT];
            float rh = sm->sr[h];
            #pragma unroll
            for (int t = 0; t < TT; t++) {
                int vt = sm->stok[cb][t];
                float acc = sm->sPT[vt * PSTR + h];
                if (vt == h) acc -= rh;
                #pragma unroll
                for (int u = 0; u < TT; u++)
                    if (u < t) acc = fmaf(sm->sC[t * TT + u], s[u], acc);
                if (c0 + t >= nsteps) acc = 0.0f;   // pad steps contribute nothing
                s[t] = acc;
            }
            // split 3xTF32 and stage A = S^T (row h = component, cols u)
            uint32_t hb[TT], lb[TT];
            #pragma unroll
            for (int t = 0; t < TT; t++) {
                uint32_t hbits = tf32b(s[t]);
                hb[t] = hbits;
                lb[t] = tf32b(s[t] - __uint_as_float(hbits));
            }
            uint4* ph = (uint4*)&sm->sAhi[h * ASTR];
            uint4* pl = (uint4*)&sm->sAlo[h * ASTR];
            #pragma unroll
            for (int q = 0; q < 4; q++) {
                ph[q] = make_uint4(hb[4*q], hb[4*q+1], hb[4*q+2], hb[4*q+3]);
                pl[q] = make_uint4(lb[4*q], lb[4*q+1], lb[4*q+2], lb[4*q+3]);
            }
        }
        __syncthreads();   // BAR 3: A staged

        // P5: rank-16 update via mma.sync; B fragments gathered pre-split (no cvt)
        #pragma unroll
        for (int kx = 0; kx < 2; kx++) {
            int u0 = kx * 8 + tig, u4 = u0 + 4;
            int t0 = sm->stok[cb][u0];
            int t4 = sm->stok[cb][u4];
            const uint32_t* bh0p = &sm->GnHi[t0 * GSTR + gid];
            const uint32_t* bh4p = &sm->GnHi[t4 * GSTR + gid];
            const uint32_t* bl0p = &sm->GnLo[t0 * GSTR + gid];
            const uint32_t* bl4p = &sm->GnLo[t4 * GSTR + gid];
            uint32_t ah0 = sm->sAhi[(m0 + gid)     * ASTR + u0];
            uint32_t ah1 = sm->sAhi[(m0 + gid + 8) * ASTR + u0];
            uint32_t ah2 = sm->sAhi[(m0 + gid)     * ASTR + u4];
            uint32_t ah3 = sm->sAhi[(m0 + gid + 8) * ASTR + u4];
            uint32_t al0 = sm->sAlo[(m0 + gid)     * ASTR + u0];
            uint32_t al1 = sm->sAlo[(m0 + gid + 8) * ASTR + u0];
            uint32_t al2 = sm->sAlo[(m0 + gid)     * ASTR + u4];
            uint32_t al3 = sm->sAlo[(m0 + gid + 8) * ASTR + u4];
            #pragma unroll
            for (int nt = 0; nt < 8; nt++) {
                uint32_t bh0 = bh0p[nt * 8], bh1 = bh4p[nt * 8];
                uint32_t bl0 = bl0p[nt * 8], bl1 = bl4p[nt * 8];
                mma8(Cacc[nt], ah0, ah1, ah2, ah3, bh0, bh1);   // hi*hi
                mma8(Cacc[nt], ah0, ah1, ah2, ah3, bl0, bl1);   // hi*lo
                mma8(Cacc[nt], al0, al1, al2, al3, bh0, bh1);   // lo*hi
            }
        }
    }

    // ---- final: dump P once more, read column v_q, logits = P[:,vq]^T Z + bias2 ----
    __syncthreads();
    #pragma unroll
    for (int nt = 0; nt < 8; nt++) {
        int r0 = m0 + gid, r1 = r0 + 8;
        int cA = nt * 8 + tig * 2, cB = cA + 1;
        sm->sPT[cA * PSTR + r0] = Cacc[nt][0];
        sm->sPT[cB * PSTR + r0] = Cacc[nt][1];
        sm->sPT[cA * PSTR + r1] = Cacc[nt][2];
        sm->sPT[cB * PSTR + r1] = Cacc[nt][3];
    }
    __syncthreads();

    if (tid < HH) {
        int n = tid;
        int vq = seqb[LL - 1];
        const float* pcol = &sm->sPT[vq * PSTR];
        float acc = d_bias2[n];
        #pragma unroll 8
        for (int i = 0; i < HH; i++)
            acc = fmaf(pcol[i], d_Z[i * HH + n], acc);
        out[b * HH + n] = acc;
    }
}

// ---------------- launch ----------------
extern "C" void kernel_launch(void* const* d_in, const int* in_sizes, int n_in,
                              void* d_out, int out_size)
{
    const int*   seq     = (const int*)  d_in[0];
    const float* embed_W = (const float*)d_in[1];
    const float* ff_w1   = (const float*)d_in[2];
    const float* ff_b1   = (const float*)d_in[3];
    const float* ff_w2   = (const float*)d_in[4];
    const float* ff_b2   = (const float*)d_in[5];
    const float* ln_g    = (const float*)d_in[6];
    const float* ln_b    = (const float*)d_in[7];
    const float* gate_w1 = (const float*)d_in[8];
    const float* gate_b1 = (const float*)d_in[9];
    const float* gate_w2 = (const float*)d_in[10];
    const float* gate_b2 = (const float*)d_in[11];
    const float* read_w  = (const float*)d_in[12];
    const float* read_b  = (const float*)d_in[13];
    const float* out_w   = (const float*)d_in[14];
    const float* out_b   = (const float*)d_in[15];

    cudaFuncSetAttribute(scan_mma, cudaFuncAttributeMaxDynamicSharedMemorySize, SMEM_BYTES);

    prekA<<<HH, 128>>>(embed_W, ff_w1, ff_b1, ff_w2, ff_b2, ln_g, ln_b,
                       gate_w1, gate_b1, gate_w2, gate_b2);
    prekB<<<HH, HH>>>(read_w, read_b, out_w, out_b);
    prekC<<<HH, HH>>>();
    scan_mma<<<BB, 128, SMEM_BYTES>>>(seq, (float*)d_out);
}

// round 13
// speedup vs baseline: 1.2652x; 1.2652x over previous
#include <cuda_runtime.h>
#include <math.h>
#include <stdint.h>

#define BB 2048
#define LL 1024
#define HH 64
#define TT 16
#define GSTR 68     // sGn fp32 row stride (floats): bank = 4*row+col -> conflict-free row reads
#define ASTR 20     // sA row stride (u32): conflict-free A fragment loads
#define BSTR 72     // staged B row stride (u32): bank = 8*t+gid -> perfectly conflict-free frags
#define PSTR 68     // sPT row stride (floats): conflict-free transposed dump

// ---------------- precomputed tables ----------------
__device__ float d_K[HH * HH];
__device__ float d_g[HH];
__device__ float d_Gn[HH * HH];      // Gn[v][j] = -a_v * (k_v . k_j)
__device__ float d_r[HH];            // r_v = ||k_v||^2 + 1e-6
__device__ float d_Y[HH * HH];
__device__ float d_Z[HH * HH];
__device__ float d_bias2[HH];

// ---------------- precompute A ----------------
__global__ void __launch_bounds__(128) prekA(
    const float* __restrict__ embed_W, const float* __restrict__ ff_w1, const float* __restrict__ ff_b1,
    const float* __restrict__ ff_w2,   const float* __restrict__ ff_b2, const float* __restrict__ ln_g,
    const float* __restrict__ ln_b,    const float* __restrict__ gate_w1, const float* __restrict__ gate_b1,
    const float* __restrict__ gate_w2, const float* __restrict__ gate_b2)
{
    int v = blockIdx.x;
    int tid = threadIdx.x;
    __shared__ float se[HH];
    __shared__ float sz[2 * HH];
    __shared__ float sk[HH];
    __shared__ float sh[16];
    __shared__ float sred[4];

    if (tid < HH) se[tid] = embed_W[v * HH + tid];
    __syncthreads();

    {
        float z = ff_b1[tid];
        #pragma unroll 8
        for (int i = 0; i < HH; i++) z = fmaf(se[i], ff_w1[i * (2 * HH) + tid], z);
        sz[tid] = fmaxf(z, 0.0f);
    }
    __syncthreads();

    if (tid < HH) {
        float ff = ff_b2[tid];
        #pragma unroll 8
        for (int j = 0; j < 2 * HH; j++) ff = fmaf(sz[j], ff_w2[j * HH + tid], ff);
        float x = se[tid] + ff;

        float s = x;
        #pragma unroll
        for (int o = 16; o > 0; o >>= 1) s += __shfl_xor_sync(0xffffffffu, s, o);
        if ((tid & 31) == 0) sred[tid >> 5] = s;
        __syncwarp();
        __syncthreads();
        float mu = (sred[0] + sred[1]) * (1.0f / HH);

        float d = x - mu;
        float sv = d * d;
        #pragma unroll
        for (int o = 16; o > 0; o >>= 1) sv += __shfl_xor_sync(0xffffffffu, sv, o);
        if ((tid & 31) == 0) sred[2 + (tid >> 5)] = sv;
        __syncwarp();
        __syncthreads();
        float var = (sred[2] + sred[3]) * (1.0f / HH);
        float inv = rsqrtf(var + 1e-5f);
        float k = d * inv * ln_g[tid] + ln_b[tid];
        sk[tid] = k;
        d_K[v * HH + tid] = k;
    }
    __syncthreads();

    if (tid < 16) {
        float hj = gate_b1[tid];
        #pragma unroll 8
        for (int i = 0; i < HH; i++) hj = fmaf(sk[i], gate_w1[i * 16 + tid], hj);
        sh[tid] = fmaxf(hj, 0.0f);
    }
    __syncthreads();
    if (tid == 0) {
        float gz = gate_b2[0];
        #pragma unroll
        for (int j = 0; j < 16; j++) gz = fmaf(sh[j], gate_w2[j], gz);
        d_g[v] = 1.0f / (1.0f + expf(-gz));
    }
}

// ---------------- tf32 split helper ----------------
__device__ __forceinline__ uint32_t tf32b(float x) {
    uint32_t r;
    asm("cvt.rna.tf32.f32 %0, %1;" : "=r"(r) : "f"(x));
    return r;
}

// ---------------- precompute B ----------------
__global__ void __launch_bounds__(64) prekB(
    const float* __restrict__ read_w, const float* __restrict__ read_b,
    const float* __restrict__ out_w,  const float* __restrict__ out_b)
{
    int v = blockIdx.x;
    int u = threadIdx.x;
    __shared__ float skv[HH];
    __shared__ float sdiag;

    skv[u] = d_K[v * HH + u];
    __syncthreads();

    float s = 0.0f;
    #pragma unroll 8
    for (int i = 0; i < HH; i++) s = fmaf(skv[i], d_K[u * HH + i], s);
    if (u == v) sdiag = s;
    __syncthreads();

    float denom = sdiag + 1e-6f;
    float a = d_g[v] / denom;
    d_Gn[v * HH + u] = -a * s;
    if (u == v) d_r[v] = denom;

    float y = 0.0f;
    #pragma unroll 8
    for (int m = 0; m < HH; m++) y = fmaf(read_w[v * HH + m], out_w[m * HH + u], y);
    d_Y[v * HH + u] = y;

    if (v == 0) {
        float b = out_b[u];
        #pragma unroll 8
        for (int m = 0; m < HH; m++) b = fmaf(read_b[m], out_w[m * HH + u], b);
        d_bias2[u] = b;
    }
}

// ---------------- precompute C ----------------
__global__ void __launch_bounds__(64) prekC()
{
    int v = blockIdx.x;
    int n = threadIdx.x;
    __shared__ float skv[HH];
    skv[n] = d_K[v * HH + n];
    __syncthreads();
    float s = 0.0f;
    #pragma unroll 8
    for (int h = 0; h < HH; h++) s = fmaf(skv[h], d_Y[h * HH + n], s);
    d_Z[v * HH + n] = s;
}

// ---------------- mma helper (baseline PTX, sm_80+) ----------------
__device__ __forceinline__ void mma8(float* c,
                                     uint32_t a0, uint32_t a1, uint32_t a2, uint32_t a3,
                                     uint32_t b0, uint32_t b1) {
    asm("mma.sync.aligned.m16n8k8.row.col.f32.tf32.tf32.f32 "
        "{%0,%1,%2,%3},{%4,%5,%6,%7},{%8,%9},{%0,%1,%2,%3};"
        : "+f"(c[0]), "+f"(c[1]), "+f"(c[2]), "+f"(c[3])
        : "r"(a0), "r"(a1), "r"(a2), "r"(a3), "r"(b0), "r"(b1));
}

// ---------------- dynamic shared layout (54.4KB -> 4 CTAs/SM) ----------------
struct SMemS {
    float    Gn[HH * GSTR];     // persistent fp32 Gn, padded rows
    float    sPT[HH * PSTR];    // P transposed: row = col-of-P
    uint32_t sAhi[HH * ASTR];   // S^T hi bits, row h, col u
    uint32_t sAlo[HH * ASTR];   // S^T lo bits
    uint32_t sBhi[TT * BSTR];   // staged B hi bits: row t (chunk-local), col n
    uint32_t sBlo[TT * BSTR];   // staged B lo bits
    float    sC[TT * TT];       // triangular coeffs
    float    sr[HH];
    int      stok[2][TT];
    short    tri[120];          // (t | u<<8) strictly-lower-triangular LUT
};
#define SMEM_BYTES ((int)sizeof(SMemS))

// ---------------- scan: chunked delta rule, P in mma register fragments ----------------
__global__ void __launch_bounds__(128) scan_mma(const int* __restrict__ seq, float* __restrict__ out)
{
    extern __shared__ __align__(16) char dynsmem[];
    SMemS* sm = (SMemS*)dynsmem;

    int tid = threadIdx.x;
    int warp = tid >> 5, lane = tid & 31;
    int gid = lane >> 2, tig = lane & 3;
    int m0 = warp * 16;
    long b = blockIdx.x;
    const int* seqb = seq + b * LL;

    // persistent fp32 table
    #pragma unroll 1
    for (int i = tid; i < HH * HH; i += 128) {
        int r = i >> 6, cc = i & 63;
        sm->Gn[r * GSTR + cc] = d_Gn[i];
    }
    if (tid < HH) sm->sr[tid] = d_r[tid];
    if (tid == 0) {
        int e = 0;
        for (int t = 1; t < TT; t++)
            for (int u = 0; u < t; u++) sm->tri[e++] = (short)(t | (u << 8));
    }

    float Cacc[8][4];
    #pragma unroll
    for (int nt = 0; nt < 8; nt++)
        #pragma unroll
        for (int q = 0; q < 4; q++) Cacc[nt][q] = 0.0f;

    const int nsteps = LL - 1;               // 1023
    const int NCH = (nsteps + TT - 1) / TT;  // 64

    int ntok = (tid < TT) ? ((tid < nsteps) ? seqb[tid] : 0) : 0;
    __syncthreads();

    #pragma unroll 1
    for (int c = 0; c < NCH; c++) {
        int c0 = c * TT;
        int cb = c & 1;

        // P1: publish this chunk's tokens; prefetch next chunk's
        if (tid < TT) {
            sm->stok[cb][tid] = ntok;
            int p = c0 + TT + tid;
            ntok = (p < nsteps) ? seqb[p] : 0;
        }
        __syncthreads();   // BAR 1: tokens visible; prev chunk fully retired

        // P3a: ALL warps dump their P rows (pre-update) transposed to sPT. Conflict-free.
        #pragma unroll
        for (int nt = 0; nt < 8; nt++) {
            int r0 = m0 + gid, r1 = r0 + 8;
            int cA = nt * 8 + tig * 2, cB = cA + 1;
            sm->sPT[cA * PSTR + r0] = Cacc[nt][0];
            sm->sPT[cB * PSTR + r0] = Cacc[nt][1];
            sm->sPT[cA * PSTR + r1] = Cacc[nt][2];
            sm->sPT[cB * PSTR + r1] = Cacc[nt][3];
        }
        // P3b: warps 2-3 build C[t][u] = Gn[v_u][v_t] (u < t), 120 entries via smem LUT
        if (warp >= 2) {
            int j = tid - 64;
            #pragma unroll 1
            for (int e = j; e < 120; e += 64) {
                int pk = sm->tri[e];
                int t = pk & 0xff, u = pk >> 8;
                sm->sC[t * TT + u] = sm->Gn[sm->stok[cb][u] * GSTR + sm->stok[cb][t]];
            }
        }
        __syncthreads();   // BAR 2: sPT + sC ready

        if (warp < 2) {
            // P4: solve; thread h handles component h.
            int h = tid;
            float s[TT];
            float rh = sm->sr[h];
            #pragma unroll
            for (int t = 0; t < TT; t++) {
                int vt = sm->stok[cb][t];
                float acc = sm->sPT[vt * PSTR + h];
                if (vt == h) acc -= rh;
                #pragma unroll
                for (int u = 0; u < TT; u++)
                    if (u < t) acc = fmaf(sm->sC[t * TT + u], s[u], acc);
                if (c0 + t >= nsteps) acc = 0.0f;   // pad steps contribute nothing
                s[t] = acc;
            }
            // split 3xTF32 and stage A = S^T (row h = component, cols u)
            uint32_t hb[TT], lb[TT];
            #pragma unroll
            for (int t = 0; t < TT; t++) {
                uint32_t hbits = tf32b(s[t]);
                hb[t] = hbits;
                lb[t] = tf32b(s[t] - __uint_as_float(hbits));
            }
            uint4* ph = (uint4*)&sm->sAhi[h * ASTR];
            uint4* pl = (uint4*)&sm->sAlo[h * ASTR];
            #pragma unroll
            for (int q = 0; q < 4; q++) {
                ph[q] = make_uint4(hb[4*q], hb[4*q+1], hb[4*q+2], hb[4*q+3]);
                pl[q] = make_uint4(lb[4*q], lb[4*q+1], lb[4*q+2], lb[4*q+3]);
            }
        } else {
            // P4b: warps 2-3 (otherwise idle) pre-split the 16 needed B rows.
            // thread j handles component j of every row t: sB[t][j] = split(Gn[v_t][j])
            int j = tid - 64;
            #pragma unroll
            for (int t = 0; t < TT; t++) {
                float g = sm->Gn[sm->stok[cb][t] * GSTR + j];
                uint32_t hbits = tf32b(g);
                sm->sBhi[t * BSTR + j] = hbits;
                sm->sBlo[t * BSTR + j] = tf32b(g - __uint_as_float(hbits));
            }
        }
        __syncthreads();   // BAR 3: A + staged B ready

        // P5: rank-16 update via mma.sync; A and B fragments pre-split (no cvt, no tokens)
        #pragma unroll
        for (int kx = 0; kx < 2; kx++) {
            int u0 = kx * 8 + tig, u4 = u0 + 4;
            const uint32_t* bh0p = &sm->sBhi[u0 * BSTR + gid];
            const uint32_t* bh4p = &sm->sBhi[u4 * BSTR + gid];
            const uint32_t* bl0p = &sm->sBlo[u0 * BSTR + gid];
            const uint32_t* bl4p = &sm->sBlo[u4 * BSTR + gid];
            uint32_t ah0 = sm->sAhi[(m0 + gid)     * ASTR + u0];
            uint32_t ah1 = sm->sAhi[(m0 + gid + 8) * ASTR + u0];
            uint32_t ah2 = sm->sAhi[(m0 + gid)     * ASTR + u4];
            uint32_t ah3 = sm->sAhi[(m0 + gid + 8) * ASTR + u4];
            uint32_t al0 = sm->sAlo[(m0 + gid)     * ASTR + u0];
            uint32_t al1 = sm->sAlo[(m0 + gid + 8) * ASTR + u0];
            uint32_t al2 = sm->sAlo[(m0 + gid)     * ASTR + u4];
            uint32_t al3 = sm->sAlo[(m0 + gid + 8) * ASTR + u4];
            #pragma unroll
            for (int nt = 0; nt < 8; nt++) {
                uint32_t bh0 = bh0p[nt * 8], bh1 = bh4p[nt * 8];
                uint32_t bl0 = bl0p[nt * 8], bl1 = bl4p[nt * 8];
                mma8(Cacc[nt], ah0, ah1, ah2, ah3, bh0, bh1);   // hi*hi
                mma8(Cacc[nt], ah0, ah1, ah2, ah3, bl0, bl1);   // hi*lo
                mma8(Cacc[nt], al0, al1, al2, al3, bh0, bh1);   // lo*hi
            }
        }
    }

    // ---- final: dump P once more, read column v_q, logits = P[:,vq]^T Z + bias2 ----
    __syncthreads();
    #pragma unroll
    for (int nt = 0; nt < 8; nt++) {
        int r0 = m0 + gid, r1 = r0 + 8;
        int cA = nt * 8 + tig * 2, cB = cA + 1;
        sm->sPT[cA * PSTR + r0] = Cacc[nt][0];
        sm->sPT[cB * PSTR + r0] = Cacc[nt][1];
        sm->sPT[cA * PSTR + r1] = Cacc[nt][2];
        sm->sPT[cB * PSTR + r1] = Cacc[nt][3];
    }
    __syncthreads();

    if (tid < HH) {
        int n = tid;
        int vq = seqb[LL - 1];
        const float* pcol = &sm->sPT[vq * PSTR];
        float acc = d_bias2[n];
        #pragma unroll 8
        for (int i = 0; i < HH; i++)
            acc = fmaf(pcol[i], d_Z[i * HH + n], acc);
        out[b * HH + n] = acc;
    }
}

// ---------------- launch ----------------
extern "C" void kernel_launch(void* const* d_in, const int* in_sizes, int n_in,
                              void* d_out, int out_size)
{
    const int*   seq     = (const int*)  d_in[0];
    const float* embed_W = (const float*)d_in[1];
    const float* ff_w1   = (const float*)d_in[2];
    const float* ff_b1   = (const float*)d_in[3];
    const float* ff_w2   = (const float*)d_in[4];
    const float* ff_b2   = (const float*)d_in[5];
    const float* ln_g    = (const float*)d_in[6];
    const float* ln_b    = (const float*)d_in[7];
    const float* gate_w1 = (const float*)d_in[8];
    const float* gate_b1 = (const float*)d_in[9];
    const float* gate_w2 = (const float*)d_in[10];
    const float* gate_b2 = (const float*)d_in[11];
    const float* read_w  = (const float*)d_in[12];
    const float* read_b  = (const float*)d_in[13];
    const float* out_w   = (const float*)d_in[14];
    const float* out_b   = (const float*)d_in[15];

    cudaFuncSetAttribute(scan_mma, cudaFuncAttributeMaxDynamicSharedMemorySize, SMEM_BYTES);

    prekA<<<HH, 128>>>(embed_W, ff_w1, ff_b1, ff_w2, ff_b2, ln_g, ln_b,
                       gate_w1, gate_b1, gate_w2, gate_b2);
    prekB<<<HH, HH>>>(read_w, read_b, out_w, out_b);
    prekC<<<HH, HH>>>();
    scan_mma<<<BB, 128, SMEM_BYTES>>>(seq, (float*)d_out);
}